// round 6
// baseline (speedup 1.0000x reference)
#include <cuda_runtime.h>
#include <math_constants.h>

#define Bc 8
#define Lc 4096
#define Hc 8
#define Dc 64
#define Sc 45
#define Uc 45
#define BHc (Bc*Hc)
#define NSPLIT 4
#define KSPLIT (Lc/NSPLIT)
#define TK 64
#define NCH 32
#define CHL (Lc/NCH)
#define KR 256                 // keys per k-range (smem tile)
#define NKR (Lc/KR)            // 16 k-ranges
#define ETOT (Lc*Sc)           // 184320 total entries (shared across bh)
#define K1_SMEM (KR*Dc*4)      // 64 KB

// ---- scratch (__device__ globals; no allocation allowed) ----
__device__ int   g_idx[ETOT];
__device__ int   g_cnt[NKR*Lc];    // counts per (krange, q)
__device__ int   g_qofs[NKR*Lc];   // absolute offsets per (krange, q)
__device__ unsigned int g_pack[ETOT];  // (kl<<18)|(q<<6)|s, sorted by (krange, q, s)
__device__ float g_slots[BHc*Lc*Sc];   // dot per (bh,q,s)  ~47MB
__device__ int   g_top[BHc*Uc];
__device__ float g_pm[BHc*Uc*NSPLIT];
__device__ float g_pl[BHc*Uc*NSPLIT];
__device__ float g_pacc[BHc*Uc*NSPLIT*Dc];
__device__ float g_ps[Bc*NCH*Hc*Dc];

// ============================================================
// b_prep: per-block redundant dtype detection (int64 vs int32),
// then thread-per-q: convert indices + per-krange counts.
// Atomic-free, replay-safe.
// ============================================================
__global__ void __launch_bounds__(256) b_prep(const void* __restrict__ raw)
{
    __shared__ unsigned int red[256];
    const unsigned int* p = (const unsigned int*)raw;
    unsigned int acc = 0;
    // OR of odd u32 words within the first ETOT words (safe for both dtypes)
    for (int j = 1 + 2*threadIdx.x; j < ETOT; j += 512) acc |= p[j];
    red[threadIdx.x] = acc;
    __syncthreads();
    for (int o = 128; o > 0; o >>= 1) {
        if (threadIdx.x < o) red[threadIdx.x] |= red[threadIdx.x + o];
        __syncthreads();
    }
    int mode64 = (red[0] == 0u) ? 1 : 0;

    int q = blockIdx.x * 256 + threadIdx.x;
    if (q >= Lc) return;
    int c[NKR];
    #pragma unroll
    for (int i = 0; i < NKR; i++) c[i] = 0;
    for (int s = 0; s < Sc; s++) {
        int v;
        if (mode64) v = (int)((const long long*)raw)[q*Sc + s];
        else        v = ((const int*)raw)[q*Sc + s];
        g_idx[q*Sc + s] = v;
        c[v >> 8]++;
    }
    #pragma unroll
    for (int i = 0; i < NKR; i++) g_cnt[i*Lc + q] = c[i];
}

// ============================================================
// b_scan: block per krange; exclusive scan over q of counts,
// plus base = total count of all lower kranges. Atomic-free.
// ============================================================
__global__ void __launch_bounds__(512) b_scan()
{
    __shared__ int part[512];
    __shared__ int sbase[512];
    int kr = blockIdx.x, t = threadIdx.x;
    // base = sum of counts of kranges < kr
    int bacc = 0;
    for (int i = t; i < kr*Lc; i += 512) bacc += g_cnt[i];
    sbase[t] = bacc;
    __syncthreads();
    for (int o = 256; o > 0; o >>= 1) {
        if (t < o) sbase[t] += sbase[t + o];
        __syncthreads();
    }
    int base = sbase[0];

    int v[8], pre[8], sum = 0;
    for (int j = 0; j < 8; j++) {
        v[j] = g_cnt[kr*Lc + t*8 + j];
        pre[j] = sum; sum += v[j];
    }
    part[t] = sum;
    __syncthreads();
    for (int off = 1; off < 512; off <<= 1) {
        int x = (t >= off) ? part[t-off] : 0;
        __syncthreads();
        part[t] += x;
        __syncthreads();
    }
    int excl = part[t] - sum;
    for (int j = 0; j < 8; j++)
        g_qofs[kr*Lc + t*8 + j] = base + excl + pre[j];
}

// ============================================================
// b_fill: thread per q, deterministic sequential cursors.
// Entries within a krange are sorted by (q, s).
// ============================================================
__global__ void __launch_bounds__(256) b_fill()
{
    int q = blockIdx.x * 256 + threadIdx.x;
    if (q >= Lc) return;
    int cur[NKR];
    #pragma unroll
    for (int i = 0; i < NKR; i++) cur[i] = g_qofs[i*Lc + q];
    for (int s = 0; s < Sc; s++) {
        int k = g_idx[q*Sc + s];
        int kr = k >> 8;
        g_pack[cur[kr]++] = ((unsigned int)(k & 255) << 18)
                          | ((unsigned int)q << 6) | (unsigned int)s;
    }
}

// ============================================================
// K1: key-tiled sampled scoring. Block = (krange, bh).
// K range (256 rows) in smem; entries streamed; Q rows via L1
// (entries q-sorted -> line reuse). 16 lanes per entry dot.
// ============================================================
__global__ void __launch_bounds__(1024) k1_scores(
    const float* __restrict__ Q, const float* __restrict__ K)
{
    extern __shared__ float4 Ks4[];   // [KR][16]
    int kr = blockIdx.x, bh = blockIdx.y;
    int b = bh >> 3, h = bh & 7;
    int tid = threadIdx.x;
    const float4* Q4 = (const float4*)Q;
    const float4* K4 = (const float4*)K;

    int kb = kr * KR;
    for (int i = tid; i < KR*16; i += 1024) {
        int row = i >> 4, part = i & 15;
        Ks4[i] = K4[(((b*Lc + kb + row)*Hc + h) << 4) + part];
    }
    __syncthreads();

    int start = g_qofs[kr*Lc];                       // offset at q=0
    int end   = (kr == NKR-1) ? ETOT : g_qofs[(kr+1)*Lc];
    int n = end - start;
    int P = (n + 1) >> 1;
    int w = tid >> 5, lane = tid & 31, half = lane >> 4, hl = lane & 15;
    const int qrow_base = (b*Lc*Hc + h) << 4;

    #pragma unroll 2
    for (int p = w; p < P; p += 32) {
        int ei = 2*p + half;
        bool valid = ei < n;
        unsigned int en = g_pack[start + (valid ? ei : n-1)];
        int kl = (int)(en >> 18);
        int q  = (int)((en >> 6) & 4095u);
        float4 ka = Ks4[kl*16 + hl];
        float4 qa = __ldg(&Q4[qrow_base + q*(Hc*16) + hl]);
        float d = qa.x*ka.x + qa.y*ka.y + qa.z*ka.z + qa.w*ka.w;
        d += __shfl_down_sync(0xffffffffu, d, 8, 16);
        d += __shfl_down_sync(0xffffffffu, d, 4, 16);
        d += __shfl_down_sync(0xffffffffu, d, 2, 16);
        d += __shfl_down_sync(0xffffffffu, d, 1, 16);
        if (hl == 0 && valid)
            g_slots[(bh*Lc + q)*Sc + (int)(en & 63u)] = d;
    }
}

// ============================================================
// K2: fused M-reduce (s-ordered) + 4-level radix top-45 (exact)
// ============================================================
__global__ void __launch_bounds__(256) k2_topk()
{
    __shared__ unsigned int keys[Lc];
    __shared__ int hist[256];
    __shared__ int sel_bin, sel_rem, cnt;
    int bh = blockIdx.x, tid = threadIdx.x;
    for (int q = tid; q < Lc; q += 256) {
        const float* sp = &g_slots[(bh*Lc + q)*Sc];
        float mx = -CUDART_INF_F, sv = 0.f;
        #pragma unroll
        for (int s = 0; s < Sc; s++) {
            float v = sp[s];
            mx = fmaxf(mx, v); sv += v;
        }
        float M = mx - sv * (1.0f/(float)Lc);
        unsigned int u = __float_as_uint(M);
        keys[q] = (u & 0x80000000u) ? ~u : (u | 0x80000000u);
    }
    if (tid == 0) cnt = 0;
    __syncthreads();
    unsigned int prefix = 0; int need = Uc;
    for (int shift = 24; shift >= 0; shift -= 8) {
        hist[tid] = 0;
        __syncthreads();
        for (int i = tid; i < Lc; i += 256) {
            unsigned int k = keys[i];
            if (shift == 24 || (k >> (shift+8)) == prefix)
                atomicAdd(&hist[(k >> shift) & 255], 1);
        }
        __syncthreads();
        if (tid == 0) {
            int c = 0;
            for (int bn = 255; bn >= 0; bn--) {
                int hcount = hist[bn];
                if (c + hcount >= need) { sel_bin = bn; sel_rem = need - c; break; }
                c += hcount;
            }
        }
        __syncthreads();
        prefix = (prefix << 8) | (unsigned int)sel_bin;
        need = sel_rem;
        __syncthreads();
    }
    for (int i = tid; i < Lc; i += 256) {
        if (keys[i] > prefix) { int p = atomicAdd(&cnt, 1); g_top[bh*Uc + p] = i; }
    }
    __syncthreads();
    for (int i = tid; i < Lc; i += 256) {
        if (keys[i] == prefix) {
            int p = atomicAdd(&cnt, 1);
            if (p < Uc) g_top[bh*Uc + p] = i;
        }
    }
}

// ============================================================
// K3: flash-style attention for the 45 selected queries (split-KV x4)
// ============================================================
__global__ void __launch_bounds__(512) k3_attn(
    const float* __restrict__ Q, const float* __restrict__ K,
    const float* __restrict__ V)
{
    __shared__ float Qs[Uc][Dc];
    __shared__ int   qpos_s[Uc];
    __shared__ float Kt[Dc][TK+1];
    __shared__ float Vt[TK][Dc];
    int split = blockIdx.x, bh = blockIdx.y;
    int b = bh >> 3, h = bh & 7;
    int tid = threadIdx.x, lane = tid & 31, w = tid >> 5;

    if (tid < Uc) qpos_s[tid] = g_top[bh*Uc + tid];
    __syncthreads();
    for (int i = tid; i < Uc*Dc; i += 512) {
        int u = i >> 6, d = i & 63;
        int qp = qpos_s[u];
        Qs[u][d] = Q[(((b*Lc + qp)*Hc + h) << 6) + d] * 0.125f;
    }
    __syncthreads();

    int maxqp = 0;
    for (int u = 0; u < Uc; u++) maxqp = max(maxqp, qpos_s[u]);
    int kb0 = split * KSPLIT;
    int ntiles = 0;
    if (maxqp >= kb0) {
        int nn = (maxqp - kb0) / TK + 1;
        ntiles = nn < (KSPLIT/TK) ? nn : (KSPLIT/TK);
    }

    float m[3], lsum[3], acc0[3], acc1[3];
    #pragma unroll
    for (int j = 0; j < 3; j++) { m[j] = -CUDART_INF_F; lsum[j]=0.f; acc0[j]=0.f; acc1[j]=0.f; }

    for (int tile = 0; tile < ntiles; tile++) {
        int kb = kb0 + tile * TK;
        for (int i = tid; i < TK*Dc; i += 512) {
            int k = i >> 6, d = i & 63;
            int gbase = (((b*Lc + kb + k)*Hc + h) << 6) + d;
            Kt[d][k] = K[gbase];
            Vt[k][d] = V[gbase];
        }
        __syncthreads();
        #pragma unroll
        for (int j = 0; j < 3; j++) {
            int u = w*3 + j;
            if (u >= Uc) continue;
            int qp = qpos_s[u];
            if (qp < kb) continue;
            int nk = min(TK, qp - kb + 1);
            float s0 = 0.f, s1 = 0.f;
            #pragma unroll 8
            for (int d = 0; d < Dc; d++) {
                float qd = Qs[u][d];
                s0 += qd * Kt[d][lane];
                s1 += qd * Kt[d][lane+32];
            }
            if (lane >= nk)      s0 = -CUDART_INF_F;
            if (lane + 32 >= nk) s1 = -CUDART_INF_F;
            float tm = fmaxf(s0, s1);
            #pragma unroll
            for (int o = 16; o > 0; o >>= 1) tm = fmaxf(tm, __shfl_xor_sync(0xffffffffu, tm, o));
            float newm = fmaxf(m[j], tm);
            float p0 = __expf(s0 - newm);
            float p1 = __expf(s1 - newm);
            float ps = p0 + p1;
            #pragma unroll
            for (int o = 16; o > 0; o >>= 1) ps += __shfl_xor_sync(0xffffffffu, ps, o);
            float c = __expf(m[j] - newm);
            lsum[j] = lsum[j]*c + ps;
            m[j] = newm;
            acc0[j] *= c; acc1[j] *= c;
            for (int k = 0; k < nk; k++) {
                float pk = __shfl_sync(0xffffffffu, (k < 32) ? p0 : p1, k & 31);
                acc0[j] += pk * Vt[k][lane];
                acc1[j] += pk * Vt[k][lane+32];
            }
        }
        __syncthreads();
    }

    #pragma unroll
    for (int j = 0; j < 3; j++) {
        int u = w*3 + j;
        if (u >= Uc) continue;
        int base = (bh*Uc + u)*NSPLIT + split;
        if (qpos_s[u] < kb0) {
            if (lane == 0) { g_pm[base] = -CUDART_INF_F; g_pl[base] = 0.f; }
            g_pacc[base*Dc + lane] = 0.f;
            g_pacc[base*Dc + lane + 32] = 0.f;
        } else {
            if (lane == 0) { g_pm[base] = m[j]; g_pl[base] = lsum[j]; }
            g_pacc[base*Dc + lane] = acc0[j];
            g_pacc[base*Dc + lane + 32] = acc1[j];
        }
    }
}

// ============================================================
// K4: chunked cumsum of V over L
// ============================================================
__global__ void __launch_bounds__(512) k4a_partials(const float* __restrict__ V)
{
    int b = blockIdx.x, ch = blockIdx.y, tid = threadIdx.x;
    float s = 0.f;
    int base = (b*Lc + ch*CHL) * (Hc*Dc) + tid;
    for (int l = 0; l < CHL; l++) s += V[base + l*(Hc*Dc)];
    g_ps[(b*NCH + ch)*(Hc*Dc) + tid] = s;
}

__global__ void __launch_bounds__(512) k4b_prefix()
{
    int b = blockIdx.x, tid = threadIdx.x;
    float run = 0.f;
    for (int ch = 0; ch < NCH; ch++) {
        int o = (b*NCH + ch)*(Hc*Dc) + tid;
        float t = g_ps[o]; g_ps[o] = run; run += t;
    }
}

__global__ void __launch_bounds__(512) k4c_cumsum(const float* __restrict__ V,
                                                  float* __restrict__ out)
{
    int b = blockIdx.x, ch = blockIdx.y, tid = threadIdx.x;
    float acc = g_ps[(b*NCH + ch)*(Hc*Dc) + tid];
    int base = (b*Lc + ch*CHL) * (Hc*Dc) + tid;
    for (int l = 0; l < CHL; l++) {
        acc += V[base + l*(Hc*Dc)];
        out[base + l*(Hc*Dc)] = acc;
    }
}

// K5: combine split-KV partials and scatter into output
__global__ void __launch_bounds__(64) k5_combine_scatter(float* __restrict__ out)
{
    int u = blockIdx.x, bh = blockIdx.y, d = threadIdx.x;
    int b = bh >> 3, h = bh & 7;
    int base = (bh*Uc + u)*NSPLIT;
    float pm[NSPLIT], pl[NSPLIT];
    float M = -CUDART_INF_F;
    #pragma unroll
    for (int s = 0; s < NSPLIT; s++) {
        pm[s] = g_pm[base+s]; pl[s] = g_pl[base+s];
        M = fmaxf(M, pm[s]);
    }
    float Ls = 0.f, r = 0.f;
    #pragma unroll
    for (int s = 0; s < NSPLIT; s++) {
        float e = __expf(pm[s] - M);
        Ls += pl[s] * e;
        r  += g_pacc[(base+s)*Dc + d] * e;
    }
    int qp = g_top[bh*Uc + u];
    out[(((b*Lc + qp)*Hc + h) << 6) + d] = r / Ls;
}

// ============================================================
extern "C" void kernel_launch(void* const* d_in, const int* in_sizes, int n_in,
                              void* d_out, int out_size)
{
    const float* Q = (const float*)d_in[0];
    const float* K = (const float*)d_in[1];
    const float* V = (const float*)d_in[2];
    const void*  IDXRAW = d_in[3];
    float* out = (float*)d_out;

    cudaFuncSetAttribute(k1_scores, cudaFuncAttributeMaxDynamicSharedMemorySize, K1_SMEM);

    b_prep<<<(Lc + 255)/256, 256>>>(IDXRAW);     // 1
    b_scan<<<NKR, 512>>>();                      // 2
    b_fill<<<(Lc + 255)/256, 256>>>();           // 3
    k1_scores<<<dim3(NKR, BHc), 1024, K1_SMEM>>>(Q, K);  // 4 <- profiled
    k2_topk<<<BHc, 256>>>();                     // 5
    k3_attn<<<dim3(NSPLIT, BHc), 512>>>(Q, K, V);// 6
    k4a_partials<<<dim3(Bc, NCH), Hc*Dc>>>(V);   // 7
    k4b_prefix<<<Bc, Hc*Dc>>>();                 // 8
    k4c_cumsum<<<dim3(Bc, NCH), Hc*Dc>>>(V, out);// 9
    k5_combine_scatter<<<dim3(Uc, BHc), Dc>>>(out); // 10
}

// round 7
// speedup vs baseline: 1.2091x; 1.2091x over previous
#include <cuda_runtime.h>
#include <math_constants.h>

#define Bc 8
#define Lc 4096
#define Hc 8
#define Dc 64
#define Sc 45
#define Uc 45
#define BHc (Bc*Hc)
#define NSPLIT 8
#define KSPLIT (Lc/NSPLIT)
#define TK 64
#define NCH 64
#define CHL (Lc/NCH)
#define KR 256                 // keys per k-range (smem tile)
#define NKR (Lc/KR)            // 16 k-ranges
#define ETOT (Lc*Sc)           // 184320 total entries (shared across bh)
#define K1_SMEM (KR*Dc*4)      // 64 KB

// ---- scratch (__device__ globals; no allocation allowed) ----
__device__ int   g_idx[ETOT];
__device__ int   g_cnt[NKR*Lc];    // counts per (krange, q)
__device__ int   g_qofs[NKR*Lc];   // absolute offsets per (krange, q)
__device__ unsigned int g_pack[ETOT];  // (kl<<18)|(q<<6)|s, sorted by (krange, q, s)
__device__ float g_slots[BHc*Lc*Sc];   // dot per (bh,q,s)
__device__ float g_M[BHc*Lc];
__device__ int   g_top[BHc*Uc];
__device__ float g_pm[BHc*Uc*NSPLIT];
__device__ float g_pl[BHc*Uc*NSPLIT];
__device__ float g_pacc[BHc*Uc*NSPLIT*Dc];
__device__ float g_ps[Bc*NCH*Hc*Dc];

// ============================================================
// b_prep: redundant per-block dtype detection, then per-q convert
// + per-krange counts. Atomic-free.
// ============================================================
__global__ void __launch_bounds__(256) b_prep(const void* __restrict__ raw)
{
    __shared__ unsigned int red[256];
    const unsigned int* p = (const unsigned int*)raw;
    unsigned int acc = 0;
    for (int j = 1 + 2*threadIdx.x; j < ETOT; j += 512) acc |= p[j];
    red[threadIdx.x] = acc;
    __syncthreads();
    for (int o = 128; o > 0; o >>= 1) {
        if (threadIdx.x < o) red[threadIdx.x] |= red[threadIdx.x + o];
        __syncthreads();
    }
    int mode64 = (red[0] == 0u) ? 1 : 0;

    int q = blockIdx.x * 256 + threadIdx.x;
    if (q >= Lc) return;
    int c[NKR];
    #pragma unroll
    for (int i = 0; i < NKR; i++) c[i] = 0;
    for (int s = 0; s < Sc; s++) {
        int v;
        if (mode64) v = (int)((const long long*)raw)[q*Sc + s];
        else        v = ((const int*)raw)[q*Sc + s];
        g_idx[q*Sc + s] = v;
        c[v >> 8]++;
    }
    #pragma unroll
    for (int i = 0; i < NKR; i++) g_cnt[i*Lc + q] = c[i];
}

// ============================================================
// b_scan: block per krange; exclusive scan over q + global base
// ============================================================
__global__ void __launch_bounds__(512) b_scan()
{
    __shared__ int part[512];
    __shared__ int sbase[512];
    int kr = blockIdx.x, t = threadIdx.x;
    int bacc = 0;
    for (int i = t; i < kr*Lc; i += 512) bacc += g_cnt[i];
    sbase[t] = bacc;
    __syncthreads();
    for (int o = 256; o > 0; o >>= 1) {
        if (t < o) sbase[t] += sbase[t + o];
        __syncthreads();
    }
    int base = sbase[0];

    int v[8], pre[8], sum = 0;
    for (int j = 0; j < 8; j++) {
        v[j] = g_cnt[kr*Lc + t*8 + j];
        pre[j] = sum; sum += v[j];
    }
    part[t] = sum;
    __syncthreads();
    for (int off = 1; off < 512; off <<= 1) {
        int x = (t >= off) ? part[t-off] : 0;
        __syncthreads();
        part[t] += x;
        __syncthreads();
    }
    int excl = part[t] - sum;
    for (int j = 0; j < 8; j++)
        g_qofs[kr*Lc + t*8 + j] = base + excl + pre[j];
}

// ============================================================
// b_fill: thread per q, deterministic sequential cursors.
// ============================================================
__global__ void __launch_bounds__(256) b_fill()
{
    int q = blockIdx.x * 256 + threadIdx.x;
    if (q >= Lc) return;
    int cur[NKR];
    #pragma unroll
    for (int i = 0; i < NKR; i++) cur[i] = g_qofs[i*Lc + q];
    for (int s = 0; s < Sc; s++) {
        int k = g_idx[q*Sc + s];
        int kr = k >> 8;
        g_pack[cur[kr]++] = ((unsigned int)(k & 255) << 18)
                          | ((unsigned int)q << 6) | (unsigned int)s;
    }
}

// ============================================================
// K1: key-tiled sampled scoring. Block = (krange, bh).
// Contiguous pair-spans per warp -> q-run reuse of the Q row in
// registers (predicated reload). K range in smem, 16 lanes/entry.
// ============================================================
__global__ void __launch_bounds__(1024) k1_scores(
    const float* __restrict__ Q, const float* __restrict__ K)
{
    extern __shared__ float4 Ks4[];   // [KR][16]
    int kr = blockIdx.x, bh = blockIdx.y;
    int b = bh >> 3, h = bh & 7;
    int tid = threadIdx.x;
    const float4* Q4 = (const float4*)Q;
    const float4* K4 = (const float4*)K;

    int kb = kr * KR;
    for (int i = tid; i < KR*16; i += 1024) {
        int row = i >> 4, part = i & 15;
        Ks4[i] = K4[(((b*Lc + kb + row)*Hc + h) << 4) + part];
    }
    __syncthreads();

    int start = g_qofs[kr*Lc];
    int end   = (kr == NKR-1) ? ETOT : g_qofs[(kr+1)*Lc];
    int n = end - start;
    int P = (n + 1) >> 1;                  // pairs
    int PPW = (P + 31) >> 5;               // pairs per warp (contiguous span)
    int w = tid >> 5, lane = tid & 31, half = lane >> 4, hl = lane & 15;
    const int qrow_base = (b*Lc*Hc + h) << 4;
    int p0 = w * PPW;
    int p1 = min(P, p0 + PPW);

    int qprev = -1;
    float4 qa = make_float4(0.f,0.f,0.f,0.f);

    #pragma unroll 4
    for (int p = p0; p < p1; p++) {
        int ei = 2*p + half;
        bool valid = ei < n;
        unsigned int en = g_pack[start + (valid ? ei : n-1)];
        int kl = (int)(en >> 18);
        int q  = (int)((en >> 6) & 4095u);
        if (q != qprev) {
            qa = __ldg(&Q4[qrow_base + (q << 7) + hl]);
            qprev = q;
        }
        float4 ka = Ks4[kl*16 + hl];
        float d = qa.x*ka.x + qa.y*ka.y + qa.z*ka.z + qa.w*ka.w;
        d += __shfl_down_sync(0xffffffffu, d, 8, 16);
        d += __shfl_down_sync(0xffffffffu, d, 4, 16);
        d += __shfl_down_sync(0xffffffffu, d, 2, 16);
        d += __shfl_down_sync(0xffffffffu, d, 1, 16);
        if (hl == 0 && valid)
            g_slots[(bh*Lc + q)*Sc + (int)(en & 63u)] = d;
    }
}

// ============================================================
// K2a: parallel M-reduce (s-ordered, matches reference)
// ============================================================
__global__ void __launch_bounds__(512) k2a_mreduce()
{
    int bh = blockIdx.y;
    int q = blockIdx.x * 512 + threadIdx.x;
    const float* sp = &g_slots[(bh*Lc + q)*Sc];
    float mx = -CUDART_INF_F, sv = 0.f;
    #pragma unroll
    for (int s = 0; s < Sc; s++) {
        float v = sp[s];
        mx = fmaxf(mx, v); sv += v;
    }
    g_M[bh*Lc + q] = mx - sv * (1.0f/(float)Lc);
}

// ============================================================
// K2: top-45 set per (b,h) via 4-level radix select (exact)
// ============================================================
__global__ void __launch_bounds__(256) k2_topk()
{
    __shared__ unsigned int keys[Lc];
    __shared__ int hist[256];
    __shared__ int sel_bin, sel_rem, cnt;
    int bh = blockIdx.x, tid = threadIdx.x;
    for (int i = tid; i < Lc; i += 256) {
        unsigned int u = __float_as_uint(g_M[bh*Lc + i]);
        keys[i] = (u & 0x80000000u) ? ~u : (u | 0x80000000u);
    }
    if (tid == 0) cnt = 0;
    __syncthreads();
    unsigned int prefix = 0; int need = Uc;
    for (int shift = 24; shift >= 0; shift -= 8) {
        hist[tid] = 0;
        __syncthreads();
        for (int i = tid; i < Lc; i += 256) {
            unsigned int k = keys[i];
            if (shift == 24 || (k >> (shift+8)) == prefix)
                atomicAdd(&hist[(k >> shift) & 255], 1);
        }
        __syncthreads();
        if (tid == 0) {
            int c = 0;
            for (int bn = 255; bn >= 0; bn--) {
                int hcount = hist[bn];
                if (c + hcount >= need) { sel_bin = bn; sel_rem = need - c; break; }
                c += hcount;
            }
        }
        __syncthreads();
        prefix = (prefix << 8) | (unsigned int)sel_bin;
        need = sel_rem;
        __syncthreads();
    }
    for (int i = tid; i < Lc; i += 256) {
        if (keys[i] > prefix) { int p = atomicAdd(&cnt, 1); g_top[bh*Uc + p] = i; }
    }
    __syncthreads();
    for (int i = tid; i < Lc; i += 256) {
        if (keys[i] == prefix) {
            int p = atomicAdd(&cnt, 1);
            if (p < Uc) g_top[bh*Uc + p] = i;
        }
    }
}

// ============================================================
// K3: flash-style attention for the 45 selected queries (split-KV x8)
// ============================================================
__global__ void __launch_bounds__(512) k3_attn(
    const float* __restrict__ Q, const float* __restrict__ K,
    const float* __restrict__ V)
{
    __shared__ float Qs[Uc][Dc];
    __shared__ int   qpos_s[Uc];
    __shared__ float Kt[Dc][TK+1];
    __shared__ float Vt[TK][Dc];
    int split = blockIdx.x, bh = blockIdx.y;
    int b = bh >> 3, h = bh & 7;
    int tid = threadIdx.x, lane = tid & 31, w = tid >> 5;

    if (tid < Uc) qpos_s[tid] = g_top[bh*Uc + tid];
    __syncthreads();
    for (int i = tid; i < Uc*Dc; i += 512) {
        int u = i >> 6, d = i & 63;
        int qp = qpos_s[u];
        Qs[u][d] = Q[(((b*Lc + qp)*Hc + h) << 6) + d] * 0.125f;
    }
    __syncthreads();

    int maxqp = 0;
    for (int u = 0; u < Uc; u++) maxqp = max(maxqp, qpos_s[u]);
    int kb0 = split * KSPLIT;
    int ntiles = 0;
    if (maxqp >= kb0) {
        int nn = (maxqp - kb0) / TK + 1;
        ntiles = nn < (KSPLIT/TK) ? nn : (KSPLIT/TK);
    }

    float m[3], lsum[3], acc0[3], acc1[3];
    #pragma unroll
    for (int j = 0; j < 3; j++) { m[j] = -CUDART_INF_F; lsum[j]=0.f; acc0[j]=0.f; acc1[j]=0.f; }

    for (int tile = 0; tile < ntiles; tile++) {
        int kb = kb0 + tile * TK;
        for (int i = tid; i < TK*Dc; i += 512) {
            int k = i >> 6, d = i & 63;
            int gbase = (((b*Lc + kb + k)*Hc + h) << 6) + d;
            Kt[d][k] = K[gbase];
            Vt[k][d] = V[gbase];
        }
        __syncthreads();
        #pragma unroll
        for (int j = 0; j < 3; j++) {
            int u = w*3 + j;
            if (u >= Uc) continue;
            int qp = qpos_s[u];
            if (qp < kb) continue;
            int nk = min(TK, qp - kb + 1);
            float s0 = 0.f, s1 = 0.f;
            #pragma unroll 8
            for (int d = 0; d < Dc; d++) {
                float qd = Qs[u][d];
                s0 += qd * Kt[d][lane];
                s1 += qd * Kt[d][lane+32];
            }
            if (lane >= nk)      s0 = -CUDART_INF_F;
            if (lane + 32 >= nk) s1 = -CUDART_INF_F;
            float tm = fmaxf(s0, s1);
            #pragma unroll
            for (int o = 16; o > 0; o >>= 1) tm = fmaxf(tm, __shfl_xor_sync(0xffffffffu, tm, o));
            float newm = fmaxf(m[j], tm);
            float p0 = __expf(s0 - newm);
            float p1 = __expf(s1 - newm);
            float ps = p0 + p1;
            #pragma unroll
            for (int o = 16; o > 0; o >>= 1) ps += __shfl_xor_sync(0xffffffffu, ps, o);
            float c = __expf(m[j] - newm);
            lsum[j] = lsum[j]*c + ps;
            m[j] = newm;
            acc0[j] *= c; acc1[j] *= c;
            for (int k = 0; k < nk; k++) {
                float pk = __shfl_sync(0xffffffffu, (k < 32) ? p0 : p1, k & 31);
                acc0[j] += pk * Vt[k][lane];
                acc1[j] += pk * Vt[k][lane+32];
            }
        }
        __syncthreads();
    }

    #pragma unroll
    for (int j = 0; j < 3; j++) {
        int u = w*3 + j;
        if (u >= Uc) continue;
        int base = (bh*Uc + u)*NSPLIT + split;
        if (qpos_s[u] < kb0) {
            if (lane == 0) { g_pm[base] = -CUDART_INF_F; g_pl[base] = 0.f; }
            g_pacc[base*Dc + lane] = 0.f;
            g_pacc[base*Dc + lane + 32] = 0.f;
        } else {
            if (lane == 0) { g_pm[base] = m[j]; g_pl[base] = lsum[j]; }
            g_pacc[base*Dc + lane] = acc0[j];
            g_pacc[base*Dc + lane + 32] = acc1[j];
        }
    }
}

// ============================================================
// K4: chunked cumsum of V over L (64 chunks)
// ============================================================
__global__ void __launch_bounds__(512) k4a_partials(const float* __restrict__ V)
{
    int b = blockIdx.x, ch = blockIdx.y, tid = threadIdx.x;
    float s = 0.f;
    int base = (b*Lc + ch*CHL) * (Hc*Dc) + tid;
    #pragma unroll 4
    for (int l = 0; l < CHL; l++) s += V[base + l*(Hc*Dc)];
    g_ps[(b*NCH + ch)*(Hc*Dc) + tid] = s;
}

__global__ void __launch_bounds__(512) k4b_prefix()
{
    int b = blockIdx.x, tid = threadIdx.x;
    float run = 0.f;
    for (int ch = 0; ch < NCH; ch++) {
        int o = (b*NCH + ch)*(Hc*Dc) + tid;
        float t = g_ps[o]; g_ps[o] = run; run += t;
    }
}

__global__ void __launch_bounds__(512) k4c_cumsum(const float* __restrict__ V,
                                                  float* __restrict__ out)
{
    int b = blockIdx.x, ch = blockIdx.y, tid = threadIdx.x;
    float acc = g_ps[(b*NCH + ch)*(Hc*Dc) + tid];
    int base = (b*Lc + ch*CHL) * (Hc*Dc) + tid;
    #pragma unroll 4
    for (int l = 0; l < CHL; l++) {
        acc += V[base + l*(Hc*Dc)];
        out[base + l*(Hc*Dc)] = acc;
    }
}

// K5: combine split-KV partials and scatter into output
__global__ void __launch_bounds__(64) k5_combine_scatter(float* __restrict__ out)
{
    int u = blockIdx.x, bh = blockIdx.y, d = threadIdx.x;
    int b = bh >> 3, h = bh & 7;
    int base = (bh*Uc + u)*NSPLIT;
    float pm[NSPLIT], pl[NSPLIT];
    float M = -CUDART_INF_F;
    #pragma unroll
    for (int s = 0; s < NSPLIT; s++) {
        pm[s] = g_pm[base+s]; pl[s] = g_pl[base+s];
        M = fmaxf(M, pm[s]);
    }
    float Ls = 0.f, r = 0.f;
    #pragma unroll
    for (int s = 0; s < NSPLIT; s++) {
        float e = __expf(pm[s] - M);
        Ls += pl[s] * e;
        r  += g_pacc[(base+s)*Dc + d] * e;
    }
    int qp = g_top[bh*Uc + u];
    out[(((b*Lc + qp)*Hc + h) << 6) + d] = r / Ls;
}

// ============================================================
extern "C" void kernel_launch(void* const* d_in, const int* in_sizes, int n_in,
                              void* d_out, int out_size)
{
    const float* Q = (const float*)d_in[0];
    const float* K = (const float*)d_in[1];
    const float* V = (const float*)d_in[2];
    const void*  IDXRAW = d_in[3];
    float* out = (float*)d_out;

    cudaFuncSetAttribute(k1_scores, cudaFuncAttributeMaxDynamicSharedMemorySize, K1_SMEM);

    b_prep<<<(Lc + 255)/256, 256>>>(IDXRAW);          // 1
    b_scan<<<NKR, 512>>>();                           // 2
    b_fill<<<(Lc + 255)/256, 256>>>();                // 3
    k1_scores<<<dim3(NKR, BHc), 1024, K1_SMEM>>>(Q, K);  // 4 <- profiled
    k2a_mreduce<<<dim3(Lc/512, BHc), 512>>>();        // 5
    k2_topk<<<BHc, 256>>>();                          // 6
    k3_attn<<<dim3(NSPLIT, BHc), 512>>>(Q, K, V);     // 7
    k4a_partials<<<dim3(Bc, NCH), Hc*Dc>>>(V);        // 8
    k4b_prefix<<<Bc, Hc*Dc>>>();                      // 9
    k4c_cumsum<<<dim3(Bc, NCH), Hc*Dc>>>(V, out);     // 10
    k5_combine_scatter<<<dim3(Uc, BHc), Dc>>>(out);   // 11
}

// round 8
// speedup vs baseline: 1.2192x; 1.0083x over previous
#include <cuda_runtime.h>
#include <math_constants.h>

#define Bc 8
#define Lc 4096
#define Hc 8
#define Dc 64
#define Sc 45
#define Uc 45
#define BHc (Bc*Hc)
#define NSPLIT 8
#define KSPLIT (Lc/NSPLIT)
#define TK 64
#define NCH 64
#define CHL (Lc/NCH)
#define KR 256                 // keys per k-range (smem tile)
#define NKR (Lc/KR)            // 16 k-ranges
#define ETOT (Lc*Sc)           // 184320 total entries (shared across bh)
#define K1_SMEM (KR*Dc*4)      // 64 KB
#define FIXSCALE 16777216.0f   // 2^24 fixed-point scale for deterministic sum

// ---- scratch (__device__ globals; no allocation allowed) ----
__device__ int   g_idx[ETOT];
__device__ int   g_cnt[NKR*Lc];
__device__ int   g_qofs[NKR*Lc];
__device__ unsigned int g_pack[ETOT];   // (q<<12)|(kl<<4), sorted by (krange,q,s)
__device__ unsigned int g_Mmax[BHc*Lc]; // monotone-mapped max of dots
__device__ unsigned long long g_Msum[BHc*Lc]; // fixed-point sum of dots
__device__ int   g_top[BHc*Uc];
__device__ float g_pm[BHc*Uc*NSPLIT];
__device__ float g_pl[BHc*Uc*NSPLIT];
__device__ float g_pacc[BHc*Uc*NSPLIT*Dc];
__device__ float g_ps[Bc*NCH*Hc*Dc];

// ============================================================
// b_prep: dtype detect + convert + per-krange counts + zero the
// (max,sum) accumulators (graph-replay safe). Atomic-free.
// ============================================================
__global__ void __launch_bounds__(256) b_prep(const void* __restrict__ raw)
{
    __shared__ unsigned int red[256];
    const unsigned int* p = (const unsigned int*)raw;
    unsigned int acc = 0;
    for (int j = 1 + 2*threadIdx.x; j < ETOT; j += 512) acc |= p[j];
    red[threadIdx.x] = acc;
    __syncthreads();
    for (int o = 128; o > 0; o >>= 1) {
        if (threadIdx.x < o) red[threadIdx.x] |= red[threadIdx.x + o];
        __syncthreads();
    }
    int mode64 = (red[0] == 0u) ? 1 : 0;

    // zero accumulators (grid-stride over all blocks of this launch)
    int nthr = gridDim.x * 256;
    for (int i = blockIdx.x*256 + threadIdx.x; i < BHc*Lc; i += nthr) {
        g_Mmax[i] = 0u;
        g_Msum[i] = 0ull;
    }

    int q = blockIdx.x * 256 + threadIdx.x;
    if (q >= Lc) return;
    int c[NKR];
    #pragma unroll
    for (int i = 0; i < NKR; i++) c[i] = 0;
    for (int s = 0; s < Sc; s++) {
        int v;
        if (mode64) v = (int)((const long long*)raw)[q*Sc + s];
        else        v = ((const int*)raw)[q*Sc + s];
        g_idx[q*Sc + s] = v;
        c[v >> 8]++;
    }
    #pragma unroll
    for (int i = 0; i < NKR; i++) g_cnt[i*Lc + q] = c[i];
}

// ============================================================
// b_scan: block per krange; exclusive scan over q + global base
// ============================================================
__global__ void __launch_bounds__(512) b_scan()
{
    __shared__ int part[512];
    __shared__ int sbase[512];
    int kr = blockIdx.x, t = threadIdx.x;
    int bacc = 0;
    for (int i = t; i < kr*Lc; i += 512) bacc += g_cnt[i];
    sbase[t] = bacc;
    __syncthreads();
    for (int o = 256; o > 0; o >>= 1) {
        if (t < o) sbase[t] += sbase[t + o];
        __syncthreads();
    }
    int base = sbase[0];

    int v[8], pre[8], sum = 0;
    for (int j = 0; j < 8; j++) {
        v[j] = g_cnt[kr*Lc + t*8 + j];
        pre[j] = sum; sum += v[j];
    }
    part[t] = sum;
    __syncthreads();
    for (int off = 1; off < 512; off <<= 1) {
        int x = (t >= off) ? part[t-off] : 0;
        __syncthreads();
        part[t] += x;
        __syncthreads();
    }
    int excl = part[t] - sum;
    for (int j = 0; j < 8; j++)
        g_qofs[kr*Lc + t*8 + j] = base + excl + pre[j];
}

// ============================================================
// b_fill: thread per q, deterministic sequential cursors.
// Entry encoding: (q<<12)|(kl<<4)
// ============================================================
__global__ void __launch_bounds__(256) b_fill()
{
    int q = blockIdx.x * 256 + threadIdx.x;
    if (q >= Lc) return;
    int cur[NKR];
    #pragma unroll
    for (int i = 0; i < NKR; i++) cur[i] = g_qofs[i*Lc + q];
    unsigned int qb = (unsigned int)q << 12;
    for (int s = 0; s < Sc; s++) {
        int k = g_idx[q*Sc + s];
        int kr = k >> 8;
        g_pack[cur[kr]++] = qb | (((unsigned int)k & 255u) << 4);
    }
}

// ============================================================
// K1: key-tiled sampled scoring. Block = (krange, bh).
// 128 groups of 8 lanes; contiguous entry spans per group ->
// q-run register reuse. Deterministic atomic max + fixed-point sum.
// ============================================================
__global__ void __launch_bounds__(1024) k1_scores(
    const float* __restrict__ Q, const float* __restrict__ K)
{
    extern __shared__ float4 Ks4[];   // [KR][16]
    int kr = blockIdx.x, bh = blockIdx.y;
    int b = bh >> 3, h = bh & 7;
    int tid = threadIdx.x;
    const float4* Q4 = (const float4*)Q;
    const float4* K4 = (const float4*)K;

    int kb = kr * KR;
    for (int i = tid; i < KR*16; i += 1024) {
        int row = i >> 4, part = i & 15;
        Ks4[i] = K4[(((b*Lc + kb + row)*Hc + h) << 4) + part];
    }
    __syncthreads();

    int start = g_qofs[kr*Lc];
    int end   = (kr == NKR-1) ? ETOT : g_qofs[(kr+1)*Lc];
    int n = end - start;
    int gid = tid >> 3, t = tid & 7;
    int per = (n + 127) >> 7;                 // entries per 8-lane group
    int e0 = gid * per;
    int e1 = min(n, e0 + per);
    const int qrow_base = ((b*Lc*Hc + h) << 4) + 2*t;
    const int mbase = bh * Lc;
    const int t2 = 2*t;

    int qprev = -1;
    float4 qa = make_float4(0.f,0.f,0.f,0.f), qb = qa;

    #pragma unroll 2
    for (int e = e0; e < e1; e++) {
        unsigned int en = g_pack[start + e];
        int q = (int)(en >> 12);
        if (q != qprev) {
            const float4* qp = &Q4[qrow_base + (q << 7)];
            qa = __ldg(qp); qb = __ldg(qp + 1);
            qprev = q;
        }
        int ki = (int)(en & 0xFF0u) + t2;
        float4 ka = Ks4[ki], kc = Ks4[ki + 1];
        float d = qa.x*ka.x + qa.y*ka.y + qa.z*ka.z + qa.w*ka.w
                + qb.x*kc.x + qb.y*kc.y + qb.z*kc.z + qb.w*kc.w;
        d += __shfl_xor_sync(0xffffffffu, d, 1, 8);
        d += __shfl_xor_sync(0xffffffffu, d, 2, 8);
        d += __shfl_xor_sync(0xffffffffu, d, 4, 8);
        if (t == 0) {
            unsigned int u = __float_as_uint(d);
            unsigned int key = (u & 0x80000000u) ? ~u : (u | 0x80000000u);
            atomicMax(&g_Mmax[mbase + q], key);
            atomicAdd(&g_Msum[mbase + q],
                      (unsigned long long)(long long)__float2ll_rn(d * FIXSCALE));
        }
    }
}

// ============================================================
// K2: compute M from (max,sum) + 4-level radix top-45 (exact)
// ============================================================
__global__ void __launch_bounds__(256) k2_topk()
{
    __shared__ unsigned int keys[Lc];
    __shared__ int hist[256];
    __shared__ int sel_bin, sel_rem, cnt;
    int bh = blockIdx.x, tid = threadIdx.x;
    for (int i = tid; i < Lc; i += 256) {
        unsigned int mk = g_Mmax[bh*Lc + i];
        unsigned int uu = (mk & 0x80000000u) ? (mk & 0x7FFFFFFFu) : ~mk;
        float mmax = __uint_as_float(uu);
        long long sll = (long long)g_Msum[bh*Lc + i];
        float M = mmax - (float)sll * (1.0f / (FIXSCALE * (float)Lc));
        unsigned int u = __float_as_uint(M);
        keys[i] = (u & 0x80000000u) ? ~u : (u | 0x80000000u);
    }
    if (tid == 0) cnt = 0;
    __syncthreads();
    unsigned int prefix = 0; int need = Uc;
    for (int shift = 24; shift >= 0; shift -= 8) {
        hist[tid] = 0;
        __syncthreads();
        for (int i = tid; i < Lc; i += 256) {
            unsigned int k = keys[i];
            if (shift == 24 || (k >> (shift+8)) == prefix)
                atomicAdd(&hist[(k >> shift) & 255], 1);
        }
        __syncthreads();
        if (tid == 0) {
            int c = 0;
            for (int bn = 255; bn >= 0; bn--) {
                int hcount = hist[bn];
                if (c + hcount >= need) { sel_bin = bn; sel_rem = need - c; break; }
                c += hcount;
            }
        }
        __syncthreads();
        prefix = (prefix << 8) | (unsigned int)sel_bin;
        need = sel_rem;
        __syncthreads();
    }
    for (int i = tid; i < Lc; i += 256) {
        if (keys[i] > prefix) { int p = atomicAdd(&cnt, 1); g_top[bh*Uc + p] = i; }
    }
    __syncthreads();
    for (int i = tid; i < Lc; i += 256) {
        if (keys[i] == prefix) {
            int p = atomicAdd(&cnt, 1);
            if (p < Uc) g_top[bh*Uc + p] = i;
        }
    }
}

// ============================================================
// K3: flash-style attention for the 45 selected queries (split-KV x8)
// ============================================================
__global__ void __launch_bounds__(512) k3_attn(
    const float* __restrict__ Q, const float* __restrict__ K,
    const float* __restrict__ V)
{
    __shared__ float Qs[Uc][Dc];
    __shared__ int   qpos_s[Uc];
    __shared__ float Kt[Dc][TK+1];
    __shared__ float Vt[TK][Dc];
    int split = blockIdx.x, bh = blockIdx.y;
    int b = bh >> 3, h = bh & 7;
    int tid = threadIdx.x, lane = tid & 31, w = tid >> 5;

    if (tid < Uc) qpos_s[tid] = g_top[bh*Uc + tid];
    __syncthreads();
    for (int i = tid; i < Uc*Dc; i += 512) {
        int u = i >> 6, d = i & 63;
        int qp = qpos_s[u];
        Qs[u][d] = Q[(((b*Lc + qp)*Hc + h) << 6) + d] * 0.125f;
    }
    __syncthreads();

    int maxqp = 0;
    for (int u = 0; u < Uc; u++) maxqp = max(maxqp, qpos_s[u]);
    int kb0 = split * KSPLIT;
    int ntiles = 0;
    if (maxqp >= kb0) {
        int nn = (maxqp - kb0) / TK + 1;
        ntiles = nn < (KSPLIT/TK) ? nn : (KSPLIT/TK);
    }

    float m[3], lsum[3], acc0[3], acc1[3];
    #pragma unroll
    for (int j = 0; j < 3; j++) { m[j] = -CUDART_INF_F; lsum[j]=0.f; acc0[j]=0.f; acc1[j]=0.f; }

    for (int tile = 0; tile < ntiles; tile++) {
        int kb = kb0 + tile * TK;
        for (int i = tid; i < TK*Dc; i += 512) {
            int k = i >> 6, d = i & 63;
            int gbase = (((b*Lc + kb + k)*Hc + h) << 6) + d;
            Kt[d][k] = K[gbase];
            Vt[k][d] = V[gbase];
        }
        __syncthreads();
        #pragma unroll
        for (int j = 0; j < 3; j++) {
            int u = w*3 + j;
            if (u >= Uc) continue;
            int qp = qpos_s[u];
            if (qp < kb) continue;
            int nk = min(TK, qp - kb + 1);
            float s0 = 0.f, s1 = 0.f;
            #pragma unroll 8
            for (int d = 0; d < Dc; d++) {
                float qd = Qs[u][d];
                s0 += qd * Kt[d][lane];
                s1 += qd * Kt[d][lane+32];
            }
            if (lane >= nk)      s0 = -CUDART_INF_F;
            if (lane + 32 >= nk) s1 = -CUDART_INF_F;
            float tm = fmaxf(s0, s1);
            #pragma unroll
            for (int o = 16; o > 0; o >>= 1) tm = fmaxf(tm, __shfl_xor_sync(0xffffffffu, tm, o));
            float newm = fmaxf(m[j], tm);
            float p0 = __expf(s0 - newm);
            float p1 = __expf(s1 - newm);
            float ps = p0 + p1;
            #pragma unroll
            for (int o = 16; o > 0; o >>= 1) ps += __shfl_xor_sync(0xffffffffu, ps, o);
            float c = __expf(m[j] - newm);
            lsum[j] = lsum[j]*c + ps;
            m[j] = newm;
            acc0[j] *= c; acc1[j] *= c;
            for (int k = 0; k < nk; k++) {
                float pk = __shfl_sync(0xffffffffu, (k < 32) ? p0 : p1, k & 31);
                acc0[j] += pk * Vt[k][lane];
                acc1[j] += pk * Vt[k][lane+32];
            }
        }
        __syncthreads();
    }

    #pragma unroll
    for (int j = 0; j < 3; j++) {
        int u = w*3 + j;
        if (u >= Uc) continue;
        int base = (bh*Uc + u)*NSPLIT + split;
        if (qpos_s[u] < kb0) {
            if (lane == 0) { g_pm[base] = -CUDART_INF_F; g_pl[base] = 0.f; }
            g_pacc[base*Dc + lane] = 0.f;
            g_pacc[base*Dc + lane + 32] = 0.f;
        } else {
            if (lane == 0) { g_pm[base] = m[j]; g_pl[base] = lsum[j]; }
            g_pacc[base*Dc + lane] = acc0[j];
            g_pacc[base*Dc + lane + 32] = acc1[j];
        }
    }
}

// ============================================================
// K4: chunked cumsum of V over L (64 chunks)
// ============================================================
__global__ void __launch_bounds__(512) k4a_partials(const float* __restrict__ V)
{
    int b = blockIdx.x, ch = blockIdx.y, tid = threadIdx.x;
    float s = 0.f;
    int base = (b*Lc + ch*CHL) * (Hc*Dc) + tid;
    #pragma unroll 4
    for (int l = 0; l < CHL; l++) s += V[base + l*(Hc*Dc)];
    g_ps[(b*NCH + ch)*(Hc*Dc) + tid] = s;
}

__global__ void __launch_bounds__(512) k4b_prefix()
{
    int b = blockIdx.x, tid = threadIdx.x;
    float run = 0.f;
    for (int ch = 0; ch < NCH; ch++) {
        int o = (b*NCH + ch)*(Hc*Dc) + tid;
        float t = g_ps[o]; g_ps[o] = run; run += t;
    }
}

__global__ void __launch_bounds__(512) k4c_cumsum(const float* __restrict__ V,
                                                  float* __restrict__ out)
{
    int b = blockIdx.x, ch = blockIdx.y, tid = threadIdx.x;
    float acc = g_ps[(b*NCH + ch)*(Hc*Dc) + tid];
    int base = (b*Lc + ch*CHL) * (Hc*Dc) + tid;
    #pragma unroll 4
    for (int l = 0; l < CHL; l++) {
        acc += V[base + l*(Hc*Dc)];
        out[base + l*(Hc*Dc)] = acc;
    }
}

// K5: combine split-KV partials and scatter into output
__global__ void __launch_bounds__(64) k5_combine_scatter(float* __restrict__ out)
{
    int u = blockIdx.x, bh = blockIdx.y, d = threadIdx.x;
    int b = bh >> 3, h = bh & 7;
    int base = (bh*Uc + u)*NSPLIT;
    float pm[NSPLIT], pl[NSPLIT];
    float M = -CUDART_INF_F;
    #pragma unroll
    for (int s = 0; s < NSPLIT; s++) {
        pm[s] = g_pm[base+s]; pl[s] = g_pl[base+s];
        M = fmaxf(M, pm[s]);
    }
    float Ls = 0.f, r = 0.f;
    #pragma unroll
    for (int s = 0; s < NSPLIT; s++) {
        float e = __expf(pm[s] - M);
        Ls += pl[s] * e;
        r  += g_pacc[(base+s)*Dc + d] * e;
    }
    int qp = g_top[bh*Uc + u];
    out[(((b*Lc + qp)*Hc + h) << 6) + d] = r / Ls;
}

// ============================================================
extern "C" void kernel_launch(void* const* d_in, const int* in_sizes, int n_in,
                              void* d_out, int out_size)
{
    const float* Q = (const float*)d_in[0];
    const float* K = (const float*)d_in[1];
    const float* V = (const float*)d_in[2];
    const void*  IDXRAW = d_in[3];
    float* out = (float*)d_out;

    cudaFuncSetAttribute(k1_scores, cudaFuncAttributeMaxDynamicSharedMemorySize, K1_SMEM);

    b_prep<<<(Lc + 255)/256, 256>>>(IDXRAW);          // 1
    b_scan<<<NKR, 512>>>();                           // 2
    b_fill<<<(Lc + 255)/256, 256>>>();                // 3
    k1_scores<<<dim3(NKR, BHc), 1024, K1_SMEM>>>(Q, K);  // 4 <- profiled
    k2_topk<<<BHc, 256>>>();                          // 5
    k3_attn<<<dim3(NSPLIT, BHc), 512>>>(Q, K, V);     // 6
    k4a_partials<<<dim3(Bc, NCH), Hc*Dc>>>(V);        // 7
    k4b_prefix<<<Bc, Hc*Dc>>>();                      // 8
    k4c_cumsum<<<dim3(Bc, NCH), Hc*Dc>>>(V, out);     // 9
    k5_combine_scatter<<<dim3(Uc, BHc), Dc>>>(out);   // 10
}

// round 9
// speedup vs baseline: 1.2443x; 1.0206x over previous
#include <cuda_runtime.h>
#include <math_constants.h>

#define Bc 8
#define Lc 4096
#define Hc 8
#define Dc 64
#define Sc 45
#define Uc 45
#define BHc (Bc*Hc)
#define NSPLIT 8
#define KSPLIT (Lc/NSPLIT)
#define TK 64
#define NCH 64
#define CHL (Lc/NCH)
#define KR 256
#define NKR (Lc/KR)
#define ETOT (Lc*Sc)
#define K1_SMEM (KR*Dc*4)
#define FIXSCALE 16777216.0f

// ---- scratch ----
__device__ int   g_idx[ETOT];
__device__ int   g_cnt[NKR*Lc];
__device__ int   g_qofs[NKR*Lc];
__device__ unsigned int g_pack[ETOT];   // (q<<12)|(kl<<4)
__device__ unsigned int g_Mmax[BHc*Lc];
__device__ unsigned long long g_Msum[BHc*Lc];
__device__ int   g_top[BHc*Uc];
__device__ float g_pm[BHc*Uc*NSPLIT];
__device__ float g_pl[BHc*Uc*NSPLIT];
__device__ float g_pacc[BHc*Uc*NSPLIT*Dc];
__device__ float g_ps[Bc*NCH*Hc*Dc];

// ============================================================
// b_prep: dtype detect (first 1024 words) + convert + counts +
// zero accumulators. 64 blocks.
// ============================================================
__global__ void __launch_bounds__(256) b_prep(const void* __restrict__ raw)
{
    __shared__ unsigned int red[256];
    const unsigned int* p = (const unsigned int*)raw;
    unsigned int acc = 0;
    for (int j = 1 + 2*threadIdx.x; j < 1024; j += 512) acc |= p[j];
    red[threadIdx.x] = acc;
    __syncthreads();
    for (int o = 128; o > 0; o >>= 1) {
        if (threadIdx.x < o) red[threadIdx.x] |= red[threadIdx.x + o];
        __syncthreads();
    }
    int mode64 = (red[0] == 0u) ? 1 : 0;

    int nthr = gridDim.x * 256;
    int gt = blockIdx.x*256 + threadIdx.x;
    for (int i = gt; i < BHc*Lc; i += nthr) {
        g_Mmax[i] = 0u;
        g_Msum[i] = 0ull;
    }

    int q = gt;
    if (q >= Lc) return;
    int c[NKR];
    #pragma unroll
    for (int i = 0; i < NKR; i++) c[i] = 0;
    for (int s = 0; s < Sc; s++) {
        int v;
        if (mode64) v = (int)((const long long*)raw)[q*Sc + s];
        else        v = ((const int*)raw)[q*Sc + s];
        g_idx[q*Sc + s] = v;
        c[v >> 8]++;
    }
    #pragma unroll
    for (int i = 0; i < NKR; i++) g_cnt[i*Lc + q] = c[i];
}

// ============================================================
// b_scan: block per krange; exclusive scan over q + global base
// ============================================================
__global__ void __launch_bounds__(512) b_scan()
{
    __shared__ int part[512];
    __shared__ int sbase[512];
    int kr = blockIdx.x, t = threadIdx.x;
    int bacc = 0;
    for (int i = t; i < kr*Lc; i += 512) bacc += g_cnt[i];
    sbase[t] = bacc;
    __syncthreads();
    for (int o = 256; o > 0; o >>= 1) {
        if (t < o) sbase[t] += sbase[t + o];
        __syncthreads();
    }
    int base = sbase[0];

    int v[8], pre[8], sum = 0;
    for (int j = 0; j < 8; j++) {
        v[j] = g_cnt[kr*Lc + t*8 + j];
        pre[j] = sum; sum += v[j];
    }
    part[t] = sum;
    __syncthreads();
    for (int off = 1; off < 512; off <<= 1) {
        int x = (t >= off) ? part[t-off] : 0;
        __syncthreads();
        part[t] += x;
        __syncthreads();
    }
    int excl = part[t] - sum;
    for (int j = 0; j < 8; j++)
        g_qofs[kr*Lc + t*8 + j] = base + excl + pre[j];
}

// ============================================================
// b_fill: thread per q, deterministic sequential cursors.
// ============================================================
__global__ void __launch_bounds__(256) b_fill()
{
    int q = blockIdx.x * 256 + threadIdx.x;
    if (q >= Lc) return;
    int cur[NKR];
    #pragma unroll
    for (int i = 0; i < NKR; i++) cur[i] = g_qofs[i*Lc + q];
    unsigned int qb = (unsigned int)q << 12;
    for (int s = 0; s < Sc; s++) {
        int k = g_idx[q*Sc + s];
        int kr = k >> 8;
        g_pack[cur[kr]++] = qb | (((unsigned int)k & 255u) << 4);
    }
}

// ============================================================
// K1: key-tiled scoring with per-q-run register accumulation.
// One atomic pair per q-run (avg 2.8 entries) instead of per entry.
// ============================================================
__global__ void __launch_bounds__(1024) k1_scores(
    const float* __restrict__ Q, const float* __restrict__ K)
{
    extern __shared__ float4 Ks4[];   // [KR][16]
    int kr = blockIdx.x, bh = blockIdx.y;
    int b = bh >> 3, h = bh & 7;
    int tid = threadIdx.x;
    const float4* Q4 = (const float4*)Q;
    const float4* K4 = (const float4*)K;

    int kb = kr * KR;
    for (int i = tid; i < KR*16; i += 1024) {
        int row = i >> 4, part = i & 15;
        Ks4[i] = K4[(((b*Lc + kb + row)*Hc + h) << 4) + part];
    }
    __syncthreads();

    int start = g_qofs[kr*Lc];
    int end   = (kr == NKR-1) ? ETOT : g_qofs[(kr+1)*Lc];
    int n = end - start;
    int gid = tid >> 3, t = tid & 7;
    int per = (n + 127) >> 7;
    int e0 = gid * per;
    int e1 = min(n, e0 + per);
    const int qrow_base = ((b*Lc*Hc + h) << 4) + 2*t;
    const int mbase = bh * Lc;
    const int t2 = 2*t;

    int qcur = -1;
    float runMax = -CUDART_INF_F, runSum = 0.f;
    float4 qa = make_float4(0.f,0.f,0.f,0.f), qb = qa;

    #pragma unroll 4
    for (int e = e0; e < e1; e++) {
        unsigned int en = g_pack[start + e];
        int q = (int)(en >> 12);
        if (q != qcur) {
            if (t == 0 && qcur >= 0) {
                unsigned int u = __float_as_uint(runMax);
                unsigned int key = (u & 0x80000000u) ? ~u : (u | 0x80000000u);
                atomicMax(&g_Mmax[mbase + qcur], key);
                atomicAdd(&g_Msum[mbase + qcur],
                          (unsigned long long)(long long)__float2ll_rn(runSum * FIXSCALE));
            }
            qcur = q;
            runMax = -CUDART_INF_F; runSum = 0.f;
            const float4* qp = &Q4[qrow_base + (q << 7)];
            qa = __ldg(qp); qb = __ldg(qp + 1);
        }
        int ki = (int)(en & 0xFF0u) + t2;
        float4 ka = Ks4[ki], kc = Ks4[ki + 1];
        float d = qa.x*ka.x + qa.y*ka.y + qa.z*ka.z + qa.w*ka.w
                + qb.x*kc.x + qb.y*kc.y + qb.z*kc.z + qb.w*kc.w;
        d += __shfl_xor_sync(0xffffffffu, d, 1, 8);
        d += __shfl_xor_sync(0xffffffffu, d, 2, 8);
        d += __shfl_xor_sync(0xffffffffu, d, 4, 8);
        runMax = fmaxf(runMax, d);
        runSum += d;
    }
    if (t == 0 && qcur >= 0) {
        unsigned int u = __float_as_uint(runMax);
        unsigned int key = (u & 0x80000000u) ? ~u : (u | 0x80000000u);
        atomicMax(&g_Mmax[mbase + qcur], key);
        atomicAdd(&g_Msum[mbase + qcur],
                  (unsigned long long)(long long)__float2ll_rn(runSum * FIXSCALE));
    }
}

// ============================================================
// K2: compute M from (max,sum) + 4-level radix top-45 (exact)
// ============================================================
__global__ void __launch_bounds__(256) k2_topk()
{
    __shared__ unsigned int keys[Lc];
    __shared__ int hist[256];
    __shared__ int sel_bin, sel_rem, cnt;
    int bh = blockIdx.x, tid = threadIdx.x;
    for (int i = tid; i < Lc; i += 256) {
        unsigned int mk = g_Mmax[bh*Lc + i];
        unsigned int uu = (mk & 0x80000000u) ? (mk & 0x7FFFFFFFu) : ~mk;
        float mmax = __uint_as_float(uu);
        long long sll = (long long)g_Msum[bh*Lc + i];
        float M = mmax - (float)sll * (1.0f / (FIXSCALE * (float)Lc));
        unsigned int u = __float_as_uint(M);
        keys[i] = (u & 0x80000000u) ? ~u : (u | 0x80000000u);
    }
    if (tid == 0) cnt = 0;
    __syncthreads();
    unsigned int prefix = 0; int need = Uc;
    for (int shift = 24; shift >= 0; shift -= 8) {
        hist[tid] = 0;
        __syncthreads();
        for (int i = tid; i < Lc; i += 256) {
            unsigned int k = keys[i];
            if (shift == 24 || (k >> (shift+8)) == prefix)
                atomicAdd(&hist[(k >> shift) & 255], 1);
        }
        __syncthreads();
        if (tid == 0) {
            int c = 0;
            for (int bn = 255; bn >= 0; bn--) {
                int hcount = hist[bn];
                if (c + hcount >= need) { sel_bin = bn; sel_rem = need - c; break; }
                c += hcount;
            }
        }
        __syncthreads();
        prefix = (prefix << 8) | (unsigned int)sel_bin;
        need = sel_rem;
        __syncthreads();
    }
    for (int i = tid; i < Lc; i += 256) {
        if (keys[i] > prefix) { int p = atomicAdd(&cnt, 1); g_top[bh*Uc + p] = i; }
    }
    __syncthreads();
    for (int i = tid; i < Lc; i += 256) {
        if (keys[i] == prefix) {
            int p = atomicAdd(&cnt, 1);
            if (p < Uc) g_top[bh*Uc + p] = i;
        }
    }
}

// ============================================================
// K3: flash-style attention for the 45 selected queries (split-KV x8)
// ============================================================
__global__ void __launch_bounds__(512) k3_attn(
    const float* __restrict__ Q, const float* __restrict__ K,
    const float* __restrict__ V)
{
    __shared__ float Qs[Uc][Dc];
    __shared__ int   qpos_s[Uc];
    __shared__ float Kt[Dc][TK+1];
    __shared__ float Vt[TK][Dc];
    int split = blockIdx.x, bh = blockIdx.y;
    int b = bh >> 3, h = bh & 7;
    int tid = threadIdx.x, lane = tid & 31, w = tid >> 5;

    if (tid < Uc) qpos_s[tid] = g_top[bh*Uc + tid];
    __syncthreads();
    for (int i = tid; i < Uc*Dc; i += 512) {
        int u = i >> 6, d = i & 63;
        int qp = qpos_s[u];
        Qs[u][d] = Q[(((b*Lc + qp)*Hc + h) << 6) + d] * 0.125f;
    }
    __syncthreads();

    int maxqp = 0;
    for (int u = 0; u < Uc; u++) maxqp = max(maxqp, qpos_s[u]);
    int kb0 = split * KSPLIT;
    int ntiles = 0;
    if (maxqp >= kb0) {
        int nn = (maxqp - kb0) / TK + 1;
        ntiles = nn < (KSPLIT/TK) ? nn : (KSPLIT/TK);
    }

    float m[3], lsum[3], acc0[3], acc1[3];
    #pragma unroll
    for (int j = 0; j < 3; j++) { m[j] = -CUDART_INF_F; lsum[j]=0.f; acc0[j]=0.f; acc1[j]=0.f; }

    for (int tile = 0; tile < ntiles; tile++) {
        int kb = kb0 + tile * TK;
        for (int i = tid; i < TK*Dc; i += 512) {
            int k = i >> 6, d = i & 63;
            int gbase = (((b*Lc + kb + k)*Hc + h) << 6) + d;
            Kt[d][k] = K[gbase];
            Vt[k][d] = V[gbase];
        }
        __syncthreads();
        #pragma unroll
        for (int j = 0; j < 3; j++) {
            int u = w*3 + j;
            if (u >= Uc) continue;
            int qp = qpos_s[u];
            if (qp < kb) continue;
            int nk = min(TK, qp - kb + 1);
            float s0 = 0.f, s1 = 0.f;
            #pragma unroll 8
            for (int d = 0; d < Dc; d++) {
                float qd = Qs[u][d];
                s0 += qd * Kt[d][lane];
                s1 += qd * Kt[d][lane+32];
            }
            if (lane >= nk)      s0 = -CUDART_INF_F;
            if (lane + 32 >= nk) s1 = -CUDART_INF_F;
            float tm = fmaxf(s0, s1);
            #pragma unroll
            for (int o = 16; o > 0; o >>= 1) tm = fmaxf(tm, __shfl_xor_sync(0xffffffffu, tm, o));
            float newm = fmaxf(m[j], tm);
            float p0 = __expf(s0 - newm);
            float p1 = __expf(s1 - newm);
            float ps = p0 + p1;
            #pragma unroll
            for (int o = 16; o > 0; o >>= 1) ps += __shfl_xor_sync(0xffffffffu, ps, o);
            float c = __expf(m[j] - newm);
            lsum[j] = lsum[j]*c + ps;
            m[j] = newm;
            acc0[j] *= c; acc1[j] *= c;
            for (int k = 0; k < nk; k++) {
                float pk = __shfl_sync(0xffffffffu, (k < 32) ? p0 : p1, k & 31);
                acc0[j] += pk * Vt[k][lane];
                acc1[j] += pk * Vt[k][lane+32];
            }
        }
        __syncthreads();
    }

    #pragma unroll
    for (int j = 0; j < 3; j++) {
        int u = w*3 + j;
        if (u >= Uc) continue;
        int base = (bh*Uc + u)*NSPLIT + split;
        if (qpos_s[u] < kb0) {
            if (lane == 0) { g_pm[base] = -CUDART_INF_F; g_pl[base] = 0.f; }
            g_pacc[base*Dc + lane] = 0.f;
            g_pacc[base*Dc + lane + 32] = 0.f;
        } else {
            if (lane == 0) { g_pm[base] = m[j]; g_pl[base] = lsum[j]; }
            g_pacc[base*Dc + lane] = acc0[j];
            g_pacc[base*Dc + lane + 32] = acc1[j];
        }
    }
}

// ============================================================
// K4: chunked cumsum of V over L (64 chunks)
// ============================================================
__global__ void __launch_bounds__(512) k4a_partials(const float* __restrict__ V)
{
    int b = blockIdx.x, ch = blockIdx.y, tid = threadIdx.x;
    float s = 0.f;
    int base = (b*Lc + ch*CHL) * (Hc*Dc) + tid;
    #pragma unroll 4
    for (int l = 0; l < CHL; l++) s += V[base + l*(Hc*Dc)];
    g_ps[(b*NCH + ch)*(Hc*Dc) + tid] = s;
}

__global__ void __launch_bounds__(512) k4b_prefix()
{
    int b = blockIdx.x, tid = threadIdx.x;
    float run = 0.f;
    for (int ch = 0; ch < NCH; ch++) {
        int o = (b*NCH + ch)*(Hc*Dc) + tid;
        float t = g_ps[o]; g_ps[o] = run; run += t;
    }
}

__global__ void __launch_bounds__(512) k4c_cumsum(const float* __restrict__ V,
                                                  float* __restrict__ out)
{
    int b = blockIdx.x, ch = blockIdx.y, tid = threadIdx.x;
    float acc = g_ps[(b*NCH + ch)*(Hc*Dc) + tid];
    int base = (b*Lc + ch*CHL) * (Hc*Dc) + tid;
    #pragma unroll 4
    for (int l = 0; l < CHL; l++) {
        acc += V[base + l*(Hc*Dc)];
        out[base + l*(Hc*Dc)] = acc;
    }
}

// K5: combine split-KV partials and scatter into output
__global__ void __launch_bounds__(64) k5_combine_scatter(float* __restrict__ out)
{
    int u = blockIdx.x, bh = blockIdx.y, d = threadIdx.x;
    int b = bh >> 3, h = bh & 7;
    int base = (bh*Uc + u)*NSPLIT;
    float pm[NSPLIT], pl[NSPLIT];
    float M = -CUDART_INF_F;
    #pragma unroll
    for (int s = 0; s < NSPLIT; s++) {
        pm[s] = g_pm[base+s]; pl[s] = g_pl[base+s];
        M = fmaxf(M, pm[s]);
    }
    float Ls = 0.f, r = 0.f;
    #pragma unroll
    for (int s = 0; s < NSPLIT; s++) {
        float e = __expf(pm[s] - M);
        Ls += pl[s] * e;
        r  += g_pacc[(base+s)*Dc + d] * e;
    }
    int qp = g_top[bh*Uc + u];
    out[(((b*Lc + qp)*Hc + h) << 6) + d] = r / Ls;
}

// ============================================================
extern "C" void kernel_launch(void* const* d_in, const int* in_sizes, int n_in,
                              void* d_out, int out_size)
{
    const float* Q = (const float*)d_in[0];
    const float* K = (const float*)d_in[1];
    const float* V = (const float*)d_in[2];
    const void*  IDXRAW = d_in[3];
    float* out = (float*)d_out;

    cudaFuncSetAttribute(k1_scores, cudaFuncAttributeMaxDynamicSharedMemorySize, K1_SMEM);

    b_prep<<<64, 256>>>(IDXRAW);                      // 1
    b_scan<<<NKR, 512>>>();                           // 2
    b_fill<<<(Lc + 255)/256, 256>>>();                // 3
    k1_scores<<<dim3(NKR, BHc), 1024, K1_SMEM>>>(Q, K);  // 4 <- profiled
    k2_topk<<<BHc, 256>>>();                          // 5
    k3_attn<<<dim3(NSPLIT, BHc), 512>>>(Q, K, V);     // 6
    k4a_partials<<<dim3(Bc, NCH), Hc*Dc>>>(V);        // 7
    k4b_prefix<<<Bc, Hc*Dc>>>();                      // 8
    k4c_cumsum<<<dim3(Bc, NCH), Hc*Dc>>>(V, out);     // 9
    k5_combine_scatter<<<dim3(Uc, BHc), Dc>>>(out);   // 10
}